// round 1
// baseline (speedup 1.0000x reference)
#include <cuda_runtime.h>

typedef unsigned long long ull;

#define NB 1024      // batch
#define TT 128       // timesteps
#define AD 8         // A dim
#define ZD 32        // z dim
#define HD 256       // hidden
#define XD 40        // AD + ZD
#define UD 128       // MLP width
#define BT 8         // batch rows per CTA
#define NTHREADS 512

// Packed fp32x2 FMA (sm_100+): two independent fp32 lanes, full fp32 precision.
__device__ __forceinline__ void fma2(ull &d, ull a, ull b) {
    asm("fma.rn.f32x2 %0, %1, %2, %0;" : "+l"(d) : "l"(a), "l"(b));
}
__device__ __forceinline__ float hsum2(ull v) {
    float lo, hi;
    asm("mov.b64 {%0, %1}, %2;" : "=f"(lo), "=f"(hi) : "l"(v));
    return lo + hi;
}
__device__ __forceinline__ float fsig(float x) { return 1.f / (1.f + __expf(-x)); }
__device__ __forceinline__ float ftanh_(float x) { return fmaf(2.f, fsig(2.f * x), -1.f); }

// One CTA owns BT=8 batch rows for all T steps. No inter-CTA communication.
// Gate GEMM: thread (hid, gh) computes 2 gate rows (gh=0 -> i,f ; gh=1 -> g,o)
// for all 8 batch rows, accumulating even/odd k in the two f32x2 lanes so
// weight pairs load directly as 64-bit words (no splat).
__global__ void __launch_bounds__(NTHREADS, 1)
lstm_guide_kernel(const float* __restrict__ A,
                  const float* __restrict__ eps,
                  const float* __restrict__ z0,
                  const float* __restrict__ h0,
                  const float* __restrict__ c0,
                  const float* __restrict__ W_ih,
                  const float* __restrict__ W_hh,
                  const float* __restrict__ b_ih,
                  const float* __restrict__ b_hh,
                  const float* __restrict__ W1,
                  const float* __restrict__ b1,
                  const float* __restrict__ W2,
                  const float* __restrict__ b2,
                  const float* __restrict__ Wz,
                  const float* __restrict__ bz,
                  float* __restrict__ Z)
{
    __shared__ __align__(16) float h_sh[BT * HD];        // [r][k]
    __shared__ __align__(16) float x_sh[BT * XD];        // [r][k]  (a | z)
    __shared__ __align__(16) float u1_sh[BT * UD];       // [r][m]
    __shared__ __align__(16) float u2_sh[BT * UD];       // [r][m]
    __shared__ __align__(16) float go_sh[2 * BT * HD];   // [0][r][hid]=tanh(g), [1][r][hid]=sig(o)
    __shared__ __align__(16) float zz_sh[BT * 2 * ZD];   // [r][j]

    const int tid = threadIdx.x;
    const int n0  = blockIdx.x * BT;
    const int hid = tid & 255;
    const int gh  = tid >> 8;

    // Gate weight rows for this thread.
    const int R0 = hid + 512 * gh;
    const int R1 = R0 + 256;
    const float* wih0 = W_ih + R0 * XD;
    const float* wih1 = W_ih + R1 * XD;
    const float* whh0 = W_hh + R0 * HD;
    const float* whh1 = W_hh + R1 * HD;
    const float bsum0 = b_ih[R0] + b_hh[R0];
    const float bsum1 = b_ih[R1] + b_hh[R1];

    // Role-constant MLP biases (roles fixed across steps).
    const float b1v = b1[tid & 127];
    const float b2v = b2[tid & 127];
    const float bzv = bz[tid & 63];

    // ---- state init ----
    for (int i = tid; i < BT * HD; i += NTHREADS) h_sh[i] = h0[i & (HD - 1)];
    if (tid < 64) {
        int r = tid >> 3, k = tid & 7;
        x_sh[r * XD + k] = A[((n0 + r) * TT + 0) * AD + k];
    } else if (tid < 320) {
        int idx = tid - 64, r = idx >> 5, j = idx & 31;
        x_sh[r * XD + AD + j] = z0[j];
    }
    float c_reg[BT];
    if (gh == 0) {
        #pragma unroll
        for (int r = 0; r < BT; ++r) c_reg[r] = c0[hid];
    }
    __syncthreads();

    const ull* hsu = (const ull*)h_sh;
    const ull* xsu = (const ull*)x_sh;

    for (int t = 0; t < TT; ++t) {
        // ================= gates =================
        ull acc0[BT], acc1[BT];
        #pragma unroll
        for (int r = 0; r < BT; ++r) { acc0[r] = 0ull; acc1[r] = 0ull; }

        #pragma unroll
        for (int k = 0; k < XD; k += 4) {
            ulonglong2 w0 = __ldg((const ulonglong2*)(wih0 + k));
            ulonglong2 w1 = __ldg((const ulonglong2*)(wih1 + k));
            #pragma unroll
            for (int r = 0; r < BT; ++r) {
                ull xa = xsu[(r * XD + k) >> 1];
                ull xb = xsu[((r * XD + k) >> 1) + 1];
                fma2(acc0[r], w0.x, xa); fma2(acc0[r], w0.y, xb);
                fma2(acc1[r], w1.x, xa); fma2(acc1[r], w1.y, xb);
            }
        }
        #pragma unroll 2
        for (int k = 0; k < HD; k += 4) {
            ulonglong2 w0 = __ldg((const ulonglong2*)(whh0 + k));
            ulonglong2 w1 = __ldg((const ulonglong2*)(whh1 + k));
            #pragma unroll
            for (int r = 0; r < BT; ++r) {
                ull ha = hsu[r * (HD / 2) + (k >> 1)];
                ull hb = hsu[r * (HD / 2) + (k >> 1) + 1];
                fma2(acc0[r], w0.x, ha); fma2(acc0[r], w0.y, hb);
                fma2(acc1[r], w1.x, ha); fma2(acc1[r], w1.y, hb);
            }
        }
        float v0[BT], v1[BT];
        #pragma unroll
        for (int r = 0; r < BT; ++r) {
            v0[r] = hsum2(acc0[r]) + bsum0;
            v1[r] = hsum2(acc1[r]) + bsum1;
        }
        if (gh == 1) {  // g,o -> activations to shared
            #pragma unroll
            for (int r = 0; r < BT; ++r) {
                go_sh[r * HD + hid]           = ftanh_(v0[r]);
                go_sh[BT * HD + r * HD + hid] = fsig(v1[r]);
            }
        }
        __syncthreads();

        // ================= LSTM cell (gh==0) + prefetch a_{t+1} =================
        if (gh == 0) {
            #pragma unroll
            for (int r = 0; r < BT; ++r) {
                float iv = fsig(v0[r]);
                float fv = fsig(v1[r]);
                float tg = go_sh[r * HD + hid];
                float ov = go_sh[BT * HD + r * HD + hid];
                float c  = fv * c_reg[r] + iv * tg;
                c_reg[r] = c;
                h_sh[r * HD + hid] = ov * ftanh_(c);
            }
        } else if (tid < 320 && t + 1 < TT) {
            int idx = tid - 256, r = idx >> 3, k = idx & 7;
            x_sh[r * XD + k] = A[((n0 + r) * TT + (t + 1)) * AD + k];
        }
        __syncthreads();

        // ================= MLP1: u1 = relu(h @ W1^T + b1) =================
        {
            const int m = tid & 127, q = tid >> 7;
            const int r0 = 2 * q, r1 = 2 * q + 1;
            const float* wp = W1 + m * HD;
            ull a0 = 0ull, a1 = 0ull;
            #pragma unroll 2
            for (int k = 0; k < HD; k += 4) {
                ulonglong2 wv = __ldg((const ulonglong2*)(wp + k));
                ull p0a = hsu[r0 * (HD / 2) + (k >> 1)], p0b = hsu[r0 * (HD / 2) + (k >> 1) + 1];
                ull p1a = hsu[r1 * (HD / 2) + (k >> 1)], p1b = hsu[r1 * (HD / 2) + (k >> 1) + 1];
                fma2(a0, wv.x, p0a); fma2(a0, wv.y, p0b);
                fma2(a1, wv.x, p1a); fma2(a1, wv.y, p1b);
            }
            u1_sh[r0 * UD + m] = fmaxf(hsum2(a0) + b1v, 0.f);
            u1_sh[r1 * UD + m] = fmaxf(hsum2(a1) + b1v, 0.f);
        }
        __syncthreads();

        // ================= MLP2 =================
        {
            const int m = tid & 127, q = tid >> 7;
            const int r0 = 2 * q, r1 = 2 * q + 1;
            const float* wp = W2 + m * UD;
            const ull* uu = (const ull*)u1_sh;
            ull a0 = 0ull, a1 = 0ull;
            #pragma unroll 2
            for (int k = 0; k < UD; k += 4) {
                ulonglong2 wv = __ldg((const ulonglong2*)(wp + k));
                ull p0a = uu[r0 * (UD / 2) + (k >> 1)], p0b = uu[r0 * (UD / 2) + (k >> 1) + 1];
                ull p1a = uu[r1 * (UD / 2) + (k >> 1)], p1b = uu[r1 * (UD / 2) + (k >> 1) + 1];
                fma2(a0, wv.x, p0a); fma2(a0, wv.y, p0b);
                fma2(a1, wv.x, p1a); fma2(a1, wv.y, p1b);
            }
            u2_sh[r0 * UD + m] = fmaxf(hsum2(a0) + b2v, 0.f);
            u2_sh[r1 * UD + m] = fmaxf(hsum2(a1) + b2v, 0.f);
        }
        __syncthreads();

        // ================= zz = u2 @ Wz^T + bz =================
        {
            const int j = tid & 63, r = tid >> 6;  // 512 tasks = 512 threads
            const float* wp = Wz + j * UD;
            const ull* uu = (const ull*)u2_sh;
            ull a0 = 0ull;
            #pragma unroll 2
            for (int k = 0; k < UD; k += 4) {
                ulonglong2 wv = __ldg((const ulonglong2*)(wp + k));
                ull pa = uu[r * (UD / 2) + (k >> 1)], pb = uu[r * (UD / 2) + (k >> 1) + 1];
                fma2(a0, wv.x, pa); fma2(a0, wv.y, pb);
            }
            zz_sh[r * (2 * ZD) + j] = hsum2(a0) + bzv;
        }
        __syncthreads();

        // ================= z_t = loc + softplus(raw) * eps_t =================
        if (tid < 256) {
            const int j = tid & 31, r = tid >> 5;
            float loc = zz_sh[r * (2 * ZD) + j];
            float sr  = zz_sh[r * (2 * ZD) + ZD + j];
            float sp  = (sr > 15.f) ? sr : log1pf(__expf(sr));
            float e   = eps[((n0 + r) * TT + t) * ZD + j];
            float zn  = fmaf(sp, e, loc);
            Z[((n0 + r) * TT + t) * ZD + j] = zn;
            x_sh[r * XD + AD + j] = zn;
        }
        __syncthreads();
    }
}

extern "C" void kernel_launch(void* const* d_in, const int* in_sizes, int n_in,
                              void* d_out, int out_size) {
    const float* A    = (const float*)d_in[0];
    const float* eps  = (const float*)d_in[1];
    const float* z0   = (const float*)d_in[2];
    const float* h0   = (const float*)d_in[3];
    const float* c0   = (const float*)d_in[4];
    const float* W_ih = (const float*)d_in[5];
    const float* W_hh = (const float*)d_in[6];
    const float* b_ih = (const float*)d_in[7];
    const float* b_hh = (const float*)d_in[8];
    const float* W1   = (const float*)d_in[9];
    const float* b1   = (const float*)d_in[10];
    const float* W2   = (const float*)d_in[11];
    const float* b2   = (const float*)d_in[12];
    const float* Wz   = (const float*)d_in[13];
    const float* bz   = (const float*)d_in[14];
    lstm_guide_kernel<<<NB / BT, NTHREADS>>>(A, eps, z0, h0, c0, W_ih, W_hh, b_ih, b_hh,
                                             W1, b1, W2, b2, Wz, bz, (float*)d_out);
}

// round 2
// speedup vs baseline: 3.2775x; 3.2775x over previous
#include <cuda_runtime.h>

typedef unsigned long long ull;

#define NB 1024      // batch
#define TT 128       // timesteps
#define AD 8         // A dim
#define ZD 32        // z dim
#define HD 256       // hidden
#define KG 296       // AD + ZD + HD  (gate GEMM k-dim)
#define KG4 74       // KG / 4
#define UD 128       // MLP width
#define BT 8         // batch rows per CTA
#define NTHREADS 512

// Permuted weight scratch (coalesced layout: [k4][row][4]).
__device__ __align__(16) float Wg_perm[KG4 * 1024 * 4];   // gates: rows 0..1023, k = [a|z|h]
__device__ __align__(16) float W1_perm[64 * 128 * 4];     // W1: 128 rows, k=256
__device__ __align__(16) float W2_perm[32 * 128 * 4];     // W2: 128 rows, k=128
__device__ __align__(16) float Wz_perm[32 * 64 * 4];      // Wz: 64 rows,  k=128

// Packed fp32x2 FMA (sm_100+): two independent fp32 lanes, full fp32 precision.
__device__ __forceinline__ void fma2(ull &d, ull a, ull b) {
    asm("fma.rn.f32x2 %0, %1, %2, %0;" : "+l"(d) : "l"(a), "l"(b));
}
__device__ __forceinline__ float hsum2(ull v) {
    float lo, hi;
    asm("mov.b64 {%0, %1}, %2;" : "=f"(lo), "=f"(hi) : "l"(v));
    return lo + hi;
}
__device__ __forceinline__ float fsig(float x) { return 1.f / (1.f + __expf(-x)); }
__device__ __forceinline__ float ftanh_(float x) { return fmaf(2.f, fsig(2.f * x), -1.f); }

// ---------------- weight permute pre-pass ----------------
__global__ void permute_weights(const float* __restrict__ W_ih,
                                const float* __restrict__ W_hh,
                                const float* __restrict__ W1,
                                const float* __restrict__ W2,
                                const float* __restrict__ Wz)
{
    const int stride = gridDim.x * blockDim.x;
    const int tid = blockIdx.x * blockDim.x + threadIdx.x;
    // gates: Wg_perm[(k4*1024 + R)*4 + j] = k<40 ? W_ih[R][k] : W_hh[R][k-40]
    for (int i = tid; i < KG4 * 1024 * 4; i += stride) {
        int j  = i & 3;
        int R  = (i >> 2) & 1023;
        int k4 = i >> 12;
        int k  = 4 * k4 + j;
        Wg_perm[i] = (k < AD + ZD) ? W_ih[R * (AD + ZD) + k] : W_hh[R * HD + (k - AD - ZD)];
    }
    for (int i = tid; i < 64 * 128 * 4; i += stride) {
        int j = i & 3; int m = (i >> 2) & 127; int k4 = i >> 9;
        W1_perm[i] = W1[m * HD + 4 * k4 + j];
    }
    for (int i = tid; i < 32 * 128 * 4; i += stride) {
        int j = i & 3; int m = (i >> 2) & 127; int k4 = i >> 9;
        W2_perm[i] = W2[m * UD + 4 * k4 + j];
    }
    for (int i = tid; i < 32 * 64 * 4; i += stride) {
        int j = i & 3; int m = (i >> 2) & 63; int k4 = i >> 8;
        Wz_perm[i] = Wz[m * UD + 4 * k4 + j];
    }
}

// ---------------- main persistent kernel ----------------
// One CTA owns BT=8 batch rows for all T steps. Activations xh = [a(8)|z(32)|h(256)]
// per row live in shared; c stays in registers (gh==0 threads).
__global__ void __launch_bounds__(NTHREADS, 1)
lstm_guide_kernel(const float* __restrict__ A,
                  const float* __restrict__ eps,
                  const float* __restrict__ z0,
                  const float* __restrict__ h0,
                  const float* __restrict__ c0,
                  const float* __restrict__ b_ih,
                  const float* __restrict__ b_hh,
                  const float* __restrict__ b1,
                  const float* __restrict__ b2,
                  const float* __restrict__ bz,
                  float* __restrict__ Z)
{
    __shared__ __align__(16) float xh_sh[BT * KG];       // [r][k]: a|z|h  (1184B rows, 16B-aligned)
    __shared__ __align__(16) float u1_sh[BT * UD];
    __shared__ __align__(16) float u2_sh[BT * UD];
    __shared__ __align__(16) float go_sh[2 * BT * HD];   // [0][r][hid]=tanh(g), [1][r][hid]=sig(o)
    __shared__ __align__(16) float zz_sh[BT * 2 * ZD];

    const int tid = threadIdx.x;
    const int n0  = blockIdx.x * BT;
    const int hid = tid & 255;
    const int gh  = tid >> 8;

    // Gate rows for this thread: gh=0 -> (i,f), gh=1 -> (g,o)
    const int R0 = hid + 512 * gh;
    const int R1 = R0 + 256;
    const float bsum0 = b_ih[R0] + b_hh[R0];
    const float bsum1 = b_ih[R1] + b_hh[R1];

    const float b1v = b1[tid & 127];
    const float b2v = b2[tid & 127];
    const float bzv = bz[tid & 63];

    // ---- state init ----
    // h part
    for (int i = tid; i < BT * HD; i += NTHREADS) {
        int r = i >> 8, k = i & 255;
        xh_sh[r * KG + (AD + ZD) + k] = h0[k];
    }
    if (tid < 64) {                       // a_0
        int r = tid >> 3, k = tid & 7;
        xh_sh[r * KG + k] = A[((n0 + r) * TT + 0) * AD + k];
    } else if (tid < 320) {               // z_0
        int idx = tid - 64, r = idx >> 5, j = idx & 31;
        xh_sh[r * KG + AD + j] = z0[j];
    }
    float c_reg[BT];
    if (gh == 0) {
        #pragma unroll
        for (int r = 0; r < BT; ++r) c_reg[r] = c0[hid];
    }
    __syncthreads();

    for (int t = 0; t < TT; ++t) {
        // ================= gates: coalesced perm-weight GEMM =================
        ull acc0[BT], acc1[BT];
        #pragma unroll
        for (int r = 0; r < BT; ++r) { acc0[r] = 0ull; acc1[r] = 0ull; }

        #pragma unroll 2
        for (int k4 = 0; k4 < KG4; ++k4) {
            const ulonglong2 w0 = *(const ulonglong2*)(Wg_perm + ((k4 << 10) + R0) * 4);
            const ulonglong2 w1 = *(const ulonglong2*)(Wg_perm + ((k4 << 10) + R1) * 4);
            #pragma unroll
            for (int r = 0; r < BT; ++r) {
                const ulonglong2 xv = *(const ulonglong2*)(xh_sh + r * KG + 4 * k4);
                fma2(acc0[r], w0.x, xv.x); fma2(acc0[r], w0.y, xv.y);
                fma2(acc1[r], w1.x, xv.x); fma2(acc1[r], w1.y, xv.y);
            }
        }
        float v0[BT], v1[BT];
        #pragma unroll
        for (int r = 0; r < BT; ++r) {
            v0[r] = hsum2(acc0[r]) + bsum0;
            v1[r] = hsum2(acc1[r]) + bsum1;
        }
        if (gh == 1) {  // g,o activations -> shared
            #pragma unroll
            for (int r = 0; r < BT; ++r) {
                go_sh[r * HD + hid]           = ftanh_(v0[r]);
                go_sh[BT * HD + r * HD + hid] = fsig(v1[r]);
            }
        }
        __syncthreads();

        // ================= LSTM cell (gh==0) + prefetch a_{t+1} =================
        if (gh == 0) {
            #pragma unroll
            for (int r = 0; r < BT; ++r) {
                float iv = fsig(v0[r]);
                float fv = fsig(v1[r]);
                float tg = go_sh[r * HD + hid];
                float ov = go_sh[BT * HD + r * HD + hid];
                float c  = fv * c_reg[r] + iv * tg;
                c_reg[r] = c;
                xh_sh[r * KG + (AD + ZD) + hid] = ov * ftanh_(c);
            }
        } else if (tid < 320 && t + 1 < TT) {
            int idx = tid - 256, r = idx >> 3, k = idx & 7;
            xh_sh[r * KG + k] = A[((n0 + r) * TT + (t + 1)) * AD + k];
        }
        __syncthreads();

        // ================= MLP1: u1 = relu(h @ W1^T + b1) =================
        {
            const int m = tid & 127, q = tid >> 7;
            const int r0 = 2 * q, r1 = 2 * q + 1;
            ull a0 = 0ull, a1 = 0ull;
            #pragma unroll 4
            for (int k4 = 0; k4 < 64; ++k4) {
                const ulonglong2 wv = *(const ulonglong2*)(W1_perm + ((k4 << 7) + m) * 4);
                const ulonglong2 p0 = *(const ulonglong2*)(xh_sh + r0 * KG + (AD + ZD) + 4 * k4);
                const ulonglong2 p1 = *(const ulonglong2*)(xh_sh + r1 * KG + (AD + ZD) + 4 * k4);
                fma2(a0, wv.x, p0.x); fma2(a0, wv.y, p0.y);
                fma2(a1, wv.x, p1.x); fma2(a1, wv.y, p1.y);
            }
            u1_sh[r0 * UD + m] = fmaxf(hsum2(a0) + b1v, 0.f);
            u1_sh[r1 * UD + m] = fmaxf(hsum2(a1) + b1v, 0.f);
        }
        __syncthreads();

        // ================= MLP2 =================
        {
            const int m = tid & 127, q = tid >> 7;
            const int r0 = 2 * q, r1 = 2 * q + 1;
            ull a0 = 0ull, a1 = 0ull;
            #pragma unroll 4
            for (int k4 = 0; k4 < 32; ++k4) {
                const ulonglong2 wv = *(const ulonglong2*)(W2_perm + ((k4 << 7) + m) * 4);
                const ulonglong2 p0 = *(const ulonglong2*)(u1_sh + r0 * UD + 4 * k4);
                const ulonglong2 p1 = *(const ulonglong2*)(u1_sh + r1 * UD + 4 * k4);
                fma2(a0, wv.x, p0.x); fma2(a0, wv.y, p0.y);
                fma2(a1, wv.x, p1.x); fma2(a1, wv.y, p1.y);
            }
            u2_sh[r0 * UD + m] = fmaxf(hsum2(a0) + b2v, 0.f);
            u2_sh[r1 * UD + m] = fmaxf(hsum2(a1) + b2v, 0.f);
        }
        __syncthreads();

        // ================= zz = u2 @ Wz^T + bz =================
        {
            const int j = tid & 63, r = tid >> 6;  // 512 tasks = 512 threads
            ull a0 = 0ull;
            #pragma unroll 4
            for (int k4 = 0; k4 < 32; ++k4) {
                const ulonglong2 wv = *(const ulonglong2*)(Wz_perm + ((k4 << 6) + j) * 4);
                const ulonglong2 pv = *(const ulonglong2*)(u2_sh + r * UD + 4 * k4);
                fma2(a0, wv.x, pv.x); fma2(a0, wv.y, pv.y);
            }
            zz_sh[r * (2 * ZD) + j] = hsum2(a0) + bzv;
        }
        __syncthreads();

        // ================= z_t = loc + softplus(raw) * eps_t =================
        if (tid < 256) {
            const int j = tid & 31, r = tid >> 5;
            float loc = zz_sh[r * (2 * ZD) + j];
            float sr  = zz_sh[r * (2 * ZD) + ZD + j];
            float sp  = (sr > 15.f) ? sr : log1pf(__expf(sr));
            float e   = eps[((n0 + r) * TT + t) * ZD + j];
            float zn  = fmaf(sp, e, loc);
            Z[((n0 + r) * TT + t) * ZD + j] = zn;
            xh_sh[r * KG + AD + j] = zn;
        }
        __syncthreads();
    }
}

extern "C" void kernel_launch(void* const* d_in, const int* in_sizes, int n_in,
                              void* d_out, int out_size) {
    const float* A    = (const float*)d_in[0];
    const float* eps  = (const float*)d_in[1];
    const float* z0   = (const float*)d_in[2];
    const float* h0   = (const float*)d_in[3];
    const float* c0   = (const float*)d_in[4];
    const float* W_ih = (const float*)d_in[5];
    const float* W_hh = (const float*)d_in[6];
    const float* b_ih = (const float*)d_in[7];
    const float* b_hh = (const float*)d_in[8];
    const float* W1   = (const float*)d_in[9];
    const float* b1   = (const float*)d_in[10];
    const float* W2   = (const float*)d_in[11];
    const float* b2   = (const float*)d_in[12];
    const float* Wz   = (const float*)d_in[13];
    const float* bz   = (const float*)d_in[14];

    permute_weights<<<148, 256>>>(W_ih, W_hh, W1, W2, Wz);
    lstm_guide_kernel<<<NB / BT, NTHREADS>>>(A, eps, z0, h0, c0,
                                             b_ih, b_hh, b1, b2, bz, (float*)d_out);
}

// round 3
// speedup vs baseline: 3.2802x; 1.0008x over previous
#include <cuda_runtime.h>

typedef unsigned long long ull;

#define NB 1024      // batch
#define TT 128       // timesteps
#define AD 8         // A dim
#define ZD 32        // z dim
#define HD 256       // hidden
#define KG 296       // AD + ZD + HD  (gate GEMM k-dim)
#define KG4 74       // KG / 4
#define UD 128       // MLP width
#define BT 8         // batch rows per CTA
#define NTHREADS 512

// Permuted weight scratch (coalesced layout: [k4][row][4]).
__device__ __align__(16) float Wg_perm[KG4 * 1024 * 4];   // gates: rows 0..1023, k = [a|z|h]
__device__ __align__(16) float W1_perm[64 * 128 * 4];     // W1: 128 rows, k=256
__device__ __align__(16) float W2_perm[32 * 128 * 4];     // W2: 128 rows, k=128
__device__ __align__(16) float Wz_perm[32 * 64 * 4];      // Wz: 64 rows,  k=128

// Packed fp32x2 FMA (sm_100+): two independent fp32 lanes, full fp32 precision.
__device__ __forceinline__ void fma2(ull &d, ull a, ull b) {
    asm("fma.rn.f32x2 %0, %1, %2, %0;" : "+l"(d) : "l"(a), "l"(b));
}
__device__ __forceinline__ float hsum2(ull v) {
    float lo, hi;
    asm("mov.b64 {%0, %1}, %2;" : "=f"(lo), "=f"(hi) : "l"(v));
    return lo + hi;
}
__device__ __forceinline__ float fsig(float x) { return 1.f / (1.f + __expf(-x)); }
__device__ __forceinline__ float ftanh_(float x) { return fmaf(2.f, fsig(2.f * x), -1.f); }

// ---------------- weight permute pre-pass ----------------
__global__ void permute_weights(const float* __restrict__ W_ih,
                                const float* __restrict__ W_hh,
                                const float* __restrict__ W1,
                                const float* __restrict__ W2,
                                const float* __restrict__ Wz)
{
    const int stride = gridDim.x * blockDim.x;
    const int tid = blockIdx.x * blockDim.x + threadIdx.x;
    // gates: Wg_perm[(k4*1024 + R)*4 + j] = k<40 ? W_ih[R][k] : W_hh[R][k-40]
    for (int i = tid; i < KG4 * 1024 * 4; i += stride) {
        int j  = i & 3;
        int R  = (i >> 2) & 1023;
        int k4 = i >> 12;
        int k  = 4 * k4 + j;
        Wg_perm[i] = (k < AD + ZD) ? W_ih[R * (AD + ZD) + k] : W_hh[R * HD + (k - AD - ZD)];
    }
    for (int i = tid; i < 64 * 128 * 4; i += stride) {
        int j = i & 3; int m = (i >> 2) & 127; int k4 = i >> 9;
        W1_perm[i] = W1[m * HD + 4 * k4 + j];
    }
    for (int i = tid; i < 32 * 128 * 4; i += stride) {
        int j = i & 3; int m = (i >> 2) & 127; int k4 = i >> 9;
        W2_perm[i] = W2[m * UD + 4 * k4 + j];
    }
    for (int i = tid; i < 32 * 64 * 4; i += stride) {
        int j = i & 3; int m = (i >> 2) & 63; int k4 = i >> 8;
        Wz_perm[i] = Wz[m * UD + 4 * k4 + j];
    }
}

// ---------------- main persistent kernel ----------------
// One CTA owns BT=8 batch rows for all T steps. Activations xh = [a(8)|z(32)|h(256)]
// per row live in shared; c stays in registers (gh==0 threads).
__global__ void __launch_bounds__(NTHREADS, 1)
lstm_guide_kernel(const float* __restrict__ A,
                  const float* __restrict__ eps,
                  const float* __restrict__ z0,
                  const float* __restrict__ h0,
                  const float* __restrict__ c0,
                  const float* __restrict__ b_ih,
                  const float* __restrict__ b_hh,
                  const float* __restrict__ b1,
                  const float* __restrict__ b2,
                  const float* __restrict__ bz,
                  float* __restrict__ Z)
{
    __shared__ __align__(16) float xh_sh[BT * KG];       // [r][k]: a|z|h  (1184B rows, 16B-aligned)
    __shared__ __align__(16) float u1_sh[BT * UD];
    __shared__ __align__(16) float u2_sh[BT * UD];
    __shared__ __align__(16) float go_sh[2 * BT * HD];   // [0][r][hid]=tanh(g), [1][r][hid]=sig(o)
    __shared__ __align__(16) float zz_sh[BT * 2 * ZD];

    const int tid = threadIdx.x;
    const int n0  = blockIdx.x * BT;
    const int hid = tid & 255;
    const int gh  = tid >> 8;

    // Gate rows for this thread: gh=0 -> (i,f), gh=1 -> (g,o)
    const int R0 = hid + 512 * gh;
    const int R1 = R0 + 256;
    const float bsum0 = b_ih[R0] + b_hh[R0];
    const float bsum1 = b_ih[R1] + b_hh[R1];

    const float b1v = b1[tid & 127];
    const float b2v = b2[tid & 127];
    const float bzv = bz[tid & 63];

    // ---- state init ----
    // h part
    for (int i = tid; i < BT * HD; i += NTHREADS) {
        int r = i >> 8, k = i & 255;
        xh_sh[r * KG + (AD + ZD) + k] = h0[k];
    }
    if (tid < 64) {                       // a_0
        int r = tid >> 3, k = tid & 7;
        xh_sh[r * KG + k] = A[((n0 + r) * TT + 0) * AD + k];
    } else if (tid < 320) {               // z_0
        int idx = tid - 64, r = idx >> 5, j = idx & 31;
        xh_sh[r * KG + AD + j] = z0[j];
    }
    float c_reg[BT];
    if (gh == 0) {
        #pragma unroll
        for (int r = 0; r < BT; ++r) c_reg[r] = c0[hid];
    }
    __syncthreads();

    for (int t = 0; t < TT; ++t) {
        // ================= gates: coalesced perm-weight GEMM =================
        ull acc0[BT], acc1[BT];
        #pragma unroll
        for (int r = 0; r < BT; ++r) { acc0[r] = 0ull; acc1[r] = 0ull; }

        #pragma unroll 2
        for (int k4 = 0; k4 < KG4; ++k4) {
            const ulonglong2 w0 = *(const ulonglong2*)(Wg_perm + ((k4 << 10) + R0) * 4);
            const ulonglong2 w1 = *(const ulonglong2*)(Wg_perm + ((k4 << 10) + R1) * 4);
            #pragma unroll
            for (int r = 0; r < BT; ++r) {
                const ulonglong2 xv = *(const ulonglong2*)(xh_sh + r * KG + 4 * k4);
                fma2(acc0[r], w0.x, xv.x); fma2(acc0[r], w0.y, xv.y);
                fma2(acc1[r], w1.x, xv.x); fma2(acc1[r], w1.y, xv.y);
            }
        }
        float v0[BT], v1[BT];
        #pragma unroll
        for (int r = 0; r < BT; ++r) {
            v0[r] = hsum2(acc0[r]) + bsum0;
            v1[r] = hsum2(acc1[r]) + bsum1;
        }
        if (gh == 1) {  // g,o activations -> shared
            #pragma unroll
            for (int r = 0; r < BT; ++r) {
                go_sh[r * HD + hid]           = ftanh_(v0[r]);
                go_sh[BT * HD + r * HD + hid] = fsig(v1[r]);
            }
        }
        __syncthreads();

        // ================= LSTM cell (gh==0) + prefetch a_{t+1} =================
        if (gh == 0) {
            #pragma unroll
            for (int r = 0; r < BT; ++r) {
                float iv = fsig(v0[r]);
                float fv = fsig(v1[r]);
                float tg = go_sh[r * HD + hid];
                float ov = go_sh[BT * HD + r * HD + hid];
                float c  = fv * c_reg[r] + iv * tg;
                c_reg[r] = c;
                xh_sh[r * KG + (AD + ZD) + hid] = ov * ftanh_(c);
            }
        } else if (tid < 320 && t + 1 < TT) {
            int idx = tid - 256, r = idx >> 3, k = idx & 7;
            xh_sh[r * KG + k] = A[((n0 + r) * TT + (t + 1)) * AD + k];
        }
        __syncthreads();

        // ================= MLP1: u1 = relu(h @ W1^T + b1) =================
        {
            const int m = tid & 127, q = tid >> 7;
            const int r0 = 2 * q, r1 = 2 * q + 1;
            ull a0 = 0ull, a1 = 0ull;
            #pragma unroll 4
            for (int k4 = 0; k4 < 64; ++k4) {
                const ulonglong2 wv = *(const ulonglong2*)(W1_perm + ((k4 << 7) + m) * 4);
                const ulonglong2 p0 = *(const ulonglong2*)(xh_sh + r0 * KG + (AD + ZD) + 4 * k4);
                const ulonglong2 p1 = *(const ulonglong2*)(xh_sh + r1 * KG + (AD + ZD) + 4 * k4);
                fma2(a0, wv.x, p0.x); fma2(a0, wv.y, p0.y);
                fma2(a1, wv.x, p1.x); fma2(a1, wv.y, p1.y);
            }
            u1_sh[r0 * UD + m] = fmaxf(hsum2(a0) + b1v, 0.f);
            u1_sh[r1 * UD + m] = fmaxf(hsum2(a1) + b1v, 0.f);
        }
        __syncthreads();

        // ================= MLP2 =================
        {
            const int m = tid & 127, q = tid >> 7;
            const int r0 = 2 * q, r1 = 2 * q + 1;
            ull a0 = 0ull, a1 = 0ull;
            #pragma unroll 4
            for (int k4 = 0; k4 < 32; ++k4) {
                const ulonglong2 wv = *(const ulonglong2*)(W2_perm + ((k4 << 7) + m) * 4);
                const ulonglong2 p0 = *(const ulonglong2*)(u1_sh + r0 * UD + 4 * k4);
                const ulonglong2 p1 = *(const ulonglong2*)(u1_sh + r1 * UD + 4 * k4);
                fma2(a0, wv.x, p0.x); fma2(a0, wv.y, p0.y);
                fma2(a1, wv.x, p1.x); fma2(a1, wv.y, p1.y);
            }
            u2_sh[r0 * UD + m] = fmaxf(hsum2(a0) + b2v, 0.f);
            u2_sh[r1 * UD + m] = fmaxf(hsum2(a1) + b2v, 0.f);
        }
        __syncthreads();

        // ================= zz = u2 @ Wz^T + bz =================
        {
            const int j = tid & 63, r = tid >> 6;  // 512 tasks = 512 threads
            ull a0 = 0ull;
            #pragma unroll 4
            for (int k4 = 0; k4 < 32; ++k4) {
                const ulonglong2 wv = *(const ulonglong2*)(Wz_perm + ((k4 << 6) + j) * 4);
                const ulonglong2 pv = *(const ulonglong2*)(u2_sh + r * UD + 4 * k4);
                fma2(a0, wv.x, pv.x); fma2(a0, wv.y, pv.y);
            }
            zz_sh[r * (2 * ZD) + j] = hsum2(a0) + bzv;
        }
        __syncthreads();

        // ================= z_t = loc + softplus(raw) * eps_t =================
        if (tid < 256) {
            const int j = tid & 31, r = tid >> 5;
            float loc = zz_sh[r * (2 * ZD) + j];
            float sr  = zz_sh[r * (2 * ZD) + ZD + j];
            float sp  = (sr > 15.f) ? sr : log1pf(__expf(sr));
            float e   = eps[((n0 + r) * TT + t) * ZD + j];
            float zn  = fmaf(sp, e, loc);
            Z[((n0 + r) * TT + t) * ZD + j] = zn;
            xh_sh[r * KG + AD + j] = zn;
        }
        __syncthreads();
    }
}

extern "C" void kernel_launch(void* const* d_in, const int* in_sizes, int n_in,
                              void* d_out, int out_size) {
    const float* A    = (const float*)d_in[0];
    const float* eps  = (const float*)d_in[1];
    const float* z0   = (const float*)d_in[2];
    const float* h0   = (const float*)d_in[3];
    const float* c0   = (const float*)d_in[4];
    const float* W_ih = (const float*)d_in[5];
    const float* W_hh = (const float*)d_in[6];
    const float* b_ih = (const float*)d_in[7];
    const float* b_hh = (const float*)d_in[8];
    const float* W1   = (const float*)d_in[9];
    const float* b1   = (const float*)d_in[10];
    const float* W2   = (const float*)d_in[11];
    const float* b2   = (const float*)d_in[12];
    const float* Wz   = (const float*)d_in[13];
    const float* bz   = (const float*)d_in[14];

    permute_weights<<<148, 256>>>(W_ih, W_hh, W1, W2, Wz);
    lstm_guide_kernel<<<NB / BT, NTHREADS>>>(A, eps, z0, h0, c0,
                                             b_ih, b_hh, b1, b2, bz, (float*)d_out);
}

// round 4
// speedup vs baseline: 3.2848x; 1.0014x over previous
#include <cuda_runtime.h>

typedef unsigned long long ull;

#define NB 1024      // batch
#define TT 128       // timesteps
#define AD 8         // A dim
#define ZD 32        // z dim
#define HD 256       // hidden
#define KG 296       // AD + ZD + HD  (gate GEMM k-dim)
#define KG4 74       // KG / 4
#define UD 128       // MLP width
#define BT 8         // batch rows per CTA
#define NTHREADS 512

// Permuted weight scratch (coalesced layout: [k4][row][4]).
__device__ __align__(16) float Wg_perm[KG4 * 1024 * 4];   // gates: rows 0..1023, k = [a|z|h]
__device__ __align__(16) float W1_perm[64 * 128 * 4];     // W1: 128 rows, k=256
__device__ __align__(16) float W2_perm[32 * 128 * 4];     // W2: 128 rows, k=128
__device__ __align__(16) float Wz_perm[32 * 64 * 4];      // Wz: 64 rows,  k=128

// Packed fp32x2 FMA (sm_100+): two independent fp32 lanes, full fp32 precision.
__device__ __forceinline__ void fma2(ull &d, ull a, ull b) {
    asm("fma.rn.f32x2 %0, %1, %2, %0;" : "+l"(d) : "l"(a), "l"(b));
}
__device__ __forceinline__ float hsum2(ull v) {
    float lo, hi;
    asm("mov.b64 {%0, %1}, %2;" : "=f"(lo), "=f"(hi) : "l"(v));
    return lo + hi;
}
__device__ __forceinline__ float fsig(float x) { return 1.f / (1.f + __expf(-x)); }
__device__ __forceinline__ float ftanh_(float x) { return fmaf(2.f, fsig(2.f * x), -1.f); }

// ---------------- weight permute pre-pass ----------------
__global__ void permute_weights(const float* __restrict__ W_ih,
                                const float* __restrict__ W_hh,
                                const float* __restrict__ W1,
                                const float* __restrict__ W2,
                                const float* __restrict__ Wz)
{
    const int stride = gridDim.x * blockDim.x;
    const int tid = blockIdx.x * blockDim.x + threadIdx.x;
    // gates: Wg_perm[(k4*1024 + R)*4 + j] = k<40 ? W_ih[R][k] : W_hh[R][k-40]
    for (int i = tid; i < KG4 * 1024 * 4; i += stride) {
        int j  = i & 3;
        int R  = (i >> 2) & 1023;
        int k4 = i >> 12;
        int k  = 4 * k4 + j;
        Wg_perm[i] = (k < AD + ZD) ? W_ih[R * (AD + ZD) + k] : W_hh[R * HD + (k - AD - ZD)];
    }
    for (int i = tid; i < 64 * 128 * 4; i += stride) {
        int j = i & 3; int m = (i >> 2) & 127; int k4 = i >> 9;
        W1_perm[i] = W1[m * HD + 4 * k4 + j];
    }
    for (int i = tid; i < 32 * 128 * 4; i += stride) {
        int j = i & 3; int m = (i >> 2) & 127; int k4 = i >> 9;
        W2_perm[i] = W2[m * UD + 4 * k4 + j];
    }
    for (int i = tid; i < 32 * 64 * 4; i += stride) {
        int j = i & 3; int m = (i >> 2) & 63; int k4 = i >> 8;
        Wz_perm[i] = Wz[m * UD + 4 * k4 + j];
    }
}

// ---------------- main persistent kernel ----------------
// One CTA owns BT=8 batch rows for all T steps. Activations xh = [a(8)|z(32)|h(256)]
// per row live in shared; c stays in registers (gh==0 threads).
__global__ void __launch_bounds__(NTHREADS, 1)
lstm_guide_kernel(const float* __restrict__ A,
                  const float* __restrict__ eps,
                  const float* __restrict__ z0,
                  const float* __restrict__ h0,
                  const float* __restrict__ c0,
                  const float* __restrict__ b_ih,
                  const float* __restrict__ b_hh,
                  const float* __restrict__ b1,
                  const float* __restrict__ b2,
                  const float* __restrict__ bz,
                  float* __restrict__ Z)
{
    __shared__ __align__(16) float xh_sh[BT * KG];       // [r][k]: a|z|h  (1184B rows, 16B-aligned)
    __shared__ __align__(16) float u1_sh[BT * UD];
    __shared__ __align__(16) float u2_sh[BT * UD];
    __shared__ __align__(16) float go_sh[2 * BT * HD];   // [0][r][hid]=tanh(g), [1][r][hid]=sig(o)
    __shared__ __align__(16) float zz_sh[BT * 2 * ZD];

    const int tid = threadIdx.x;
    const int n0  = blockIdx.x * BT;
    const int hid = tid & 255;
    const int gh  = tid >> 8;

    // Gate rows for this thread: gh=0 -> (i,f), gh=1 -> (g,o)
    const int R0 = hid + 512 * gh;
    const int R1 = R0 + 256;
    const float bsum0 = b_ih[R0] + b_hh[R0];
    const float bsum1 = b_ih[R1] + b_hh[R1];

    const float b1v = b1[tid & 127];
    const float b2v = b2[tid & 127];
    const float bzv = bz[tid & 63];

    // ---- state init ----
    // h part
    for (int i = tid; i < BT * HD; i += NTHREADS) {
        int r = i >> 8, k = i & 255;
        xh_sh[r * KG + (AD + ZD) + k] = h0[k];
    }
    if (tid < 64) {                       // a_0
        int r = tid >> 3, k = tid & 7;
        xh_sh[r * KG + k] = A[((n0 + r) * TT + 0) * AD + k];
    } else if (tid < 320) {               // z_0
        int idx = tid - 64, r = idx >> 5, j = idx & 31;
        xh_sh[r * KG + AD + j] = z0[j];
    }
    float c_reg[BT];
    if (gh == 0) {
        #pragma unroll
        for (int r = 0; r < BT; ++r) c_reg[r] = c0[hid];
    }
    __syncthreads();

    for (int t = 0; t < TT; ++t) {
        // ================= gates: coalesced perm-weight GEMM =================
        ull acc0[BT], acc1[BT];
        #pragma unroll
        for (int r = 0; r < BT; ++r) { acc0[r] = 0ull; acc1[r] = 0ull; }

        #pragma unroll 2
        for (int k4 = 0; k4 < KG4; ++k4) {
            const ulonglong2 w0 = *(const ulonglong2*)(Wg_perm + ((k4 << 10) + R0) * 4);
            const ulonglong2 w1 = *(const ulonglong2*)(Wg_perm + ((k4 << 10) + R1) * 4);
            #pragma unroll
            for (int r = 0; r < BT; ++r) {
                const ulonglong2 xv = *(const ulonglong2*)(xh_sh + r * KG + 4 * k4);
                fma2(acc0[r], w0.x, xv.x); fma2(acc0[r], w0.y, xv.y);
                fma2(acc1[r], w1.x, xv.x); fma2(acc1[r], w1.y, xv.y);
            }
        }
        float v0[BT], v1[BT];
        #pragma unroll
        for (int r = 0; r < BT; ++r) {
            v0[r] = hsum2(acc0[r]) + bsum0;
            v1[r] = hsum2(acc1[r]) + bsum1;
        }
        if (gh == 1) {  // g,o activations -> shared
            #pragma unroll
            for (int r = 0; r < BT; ++r) {
                go_sh[r * HD + hid]           = ftanh_(v0[r]);
                go_sh[BT * HD + r * HD + hid] = fsig(v1[r]);
            }
        }
        __syncthreads();

        // ================= LSTM cell (gh==0) + prefetch a_{t+1} =================
        if (gh == 0) {
            #pragma unroll
            for (int r = 0; r < BT; ++r) {
                float iv = fsig(v0[r]);
                float fv = fsig(v1[r]);
                float tg = go_sh[r * HD + hid];
                float ov = go_sh[BT * HD + r * HD + hid];
                float c  = fv * c_reg[r] + iv * tg;
                c_reg[r] = c;
                xh_sh[r * KG + (AD + ZD) + hid] = ov * ftanh_(c);
            }
        } else if (tid < 320 && t + 1 < TT) {
            int idx = tid - 256, r = idx >> 3, k = idx & 7;
            xh_sh[r * KG + k] = A[((n0 + r) * TT + (t + 1)) * AD + k];
        }
        __syncthreads();

        // ================= MLP1: u1 = relu(h @ W1^T + b1) =================
        {
            const int m = tid & 127, q = tid >> 7;
            const int r0 = 2 * q, r1 = 2 * q + 1;
            ull a0 = 0ull, a1 = 0ull;
            #pragma unroll 4
            for (int k4 = 0; k4 < 64; ++k4) {
                const ulonglong2 wv = *(const ulonglong2*)(W1_perm + ((k4 << 7) + m) * 4);
                const ulonglong2 p0 = *(const ulonglong2*)(xh_sh + r0 * KG + (AD + ZD) + 4 * k4);
                const ulonglong2 p1 = *(const ulonglong2*)(xh_sh + r1 * KG + (AD + ZD) + 4 * k4);
                fma2(a0, wv.x, p0.x); fma2(a0, wv.y, p0.y);
                fma2(a1, wv.x, p1.x); fma2(a1, wv.y, p1.y);
            }
            u1_sh[r0 * UD + m] = fmaxf(hsum2(a0) + b1v, 0.f);
            u1_sh[r1 * UD + m] = fmaxf(hsum2(a1) + b1v, 0.f);
        }
        __syncthreads();

        // ================= MLP2 =================
        {
            const int m = tid & 127, q = tid >> 7;
            const int r0 = 2 * q, r1 = 2 * q + 1;
            ull a0 = 0ull, a1 = 0ull;
            #pragma unroll 4
            for (int k4 = 0; k4 < 32; ++k4) {
                const ulonglong2 wv = *(const ulonglong2*)(W2_perm + ((k4 << 7) + m) * 4);
                const ulonglong2 p0 = *(const ulonglong2*)(u1_sh + r0 * UD + 4 * k4);
                const ulonglong2 p1 = *(const ulonglong2*)(u1_sh + r1 * UD + 4 * k4);
                fma2(a0, wv.x, p0.x); fma2(a0, wv.y, p0.y);
                fma2(a1, wv.x, p1.x); fma2(a1, wv.y, p1.y);
            }
            u2_sh[r0 * UD + m] = fmaxf(hsum2(a0) + b2v, 0.f);
            u2_sh[r1 * UD + m] = fmaxf(hsum2(a1) + b2v, 0.f);
        }
        __syncthreads();

        // ================= zz = u2 @ Wz^T + bz =================
        {
            const int j = tid & 63, r = tid >> 6;  // 512 tasks = 512 threads
            ull a0 = 0ull;
            #pragma unroll 4
            for (int k4 = 0; k4 < 32; ++k4) {
                const ulonglong2 wv = *(const ulonglong2*)(Wz_perm + ((k4 << 6) + j) * 4);
                const ulonglong2 pv = *(const ulonglong2*)(u2_sh + r * UD + 4 * k4);
                fma2(a0, wv.x, pv.x); fma2(a0, wv.y, pv.y);
            }
            zz_sh[r * (2 * ZD) + j] = hsum2(a0) + bzv;
        }
        __syncthreads();

        // ================= z_t = loc + softplus(raw) * eps_t =================
        if (tid < 256) {
            const int j = tid & 31, r = tid >> 5;
            float loc = zz_sh[r * (2 * ZD) + j];
            float sr  = zz_sh[r * (2 * ZD) + ZD + j];
            float sp  = (sr > 15.f) ? sr : log1pf(__expf(sr));
            float e   = eps[((n0 + r) * TT + t) * ZD + j];
            float zn  = fmaf(sp, e, loc);
            Z[((n0 + r) * TT + t) * ZD + j] = zn;
            xh_sh[r * KG + AD + j] = zn;
        }
        __syncthreads();
    }
}

extern "C" void kernel_launch(void* const* d_in, const int* in_sizes, int n_in,
                              void* d_out, int out_size) {
    const float* A    = (const float*)d_in[0];
    const float* eps  = (const float*)d_in[1];
    const float* z0   = (const float*)d_in[2];
    const float* h0   = (const float*)d_in[3];
    const float* c0   = (const float*)d_in[4];
    const float* W_ih = (const float*)d_in[5];
    const float* W_hh = (const float*)d_in[6];
    const float* b_ih = (const float*)d_in[7];
    const float* b_hh = (const float*)d_in[8];
    const float* W1   = (const float*)d_in[9];
    const float* b1   = (const float*)d_in[10];
    const float* W2   = (const float*)d_in[11];
    const float* b2   = (const float*)d_in[12];
    const float* Wz   = (const float*)d_in[13];
    const float* bz   = (const float*)d_in[14];

    permute_weights<<<148, 256>>>(W_ih, W_hh, W1, W2, Wz);
    lstm_guide_kernel<<<NB / BT, NTHREADS>>>(A, eps, z0, h0, c0,
                                             b_ih, b_hh, b1, b2, bz, (float*)d_out);
}